// round 14
// baseline (speedup 1.0000x reference)
#include <cuda_runtime.h>
#include <math.h>

#define BB   2
#define NNODE 2048
#define HID  256
#define NH   4
#define DD   64
#define PL   128

// ---------------- scratch (device globals; no allocation allowed) ----------------
__device__ float g_x0[BB*NNODE*HID];       // input-proj output (4 MB)
__device__ float g_h[BB*NNODE*HID];        // per-layer projected features (4 MB)
__device__ float4 g_spk[BB*NNODE*NH];      // (src, exp(src), exp(.2src), 0)
__device__ float4 g_dpk[BB*NNODE*NH];      // (dst, exp(dst), exp(.2dst), 0)
__device__ float g_partial[BB*128*HID];    // pool partial weighted sums (unnormalized)
__device__ float g_zpart[BB*128];          // pool partial Z

// ---------------- packed f32x2 helpers (sm_103a) ----------------
__device__ __forceinline__ unsigned long long pack2(float v) {
    unsigned long long r;
    asm("mov.b64 %0, {%1, %1};" : "=l"(r) : "f"(v));
    return r;
}
__device__ __forceinline__ void unpack2(unsigned long long v, float& lo, float& hi) {
    asm("mov.b64 {%0, %1}, %2;" : "=f"(lo), "=f"(hi) : "l"(v));
}
__device__ __forceinline__ unsigned long long fma2(unsigned long long a,
                                                   unsigned long long b,
                                                   unsigned long long c) {
    unsigned long long d;
    asm("fma.rn.f32x2 %0, %1, %2, %3;" : "=l"(d) : "l"(a), "l"(b), "l"(c));
    return d;
}
__device__ __forceinline__ unsigned long long add2(unsigned long long a,
                                                   unsigned long long b) {
    unsigned long long d;
    asm("add.rn.f32x2 %0, %1, %2;" : "=l"(d) : "l"(a), "l"(b));
    return d;
}
__device__ __forceinline__ unsigned int smem_u32(const void* p) {
    unsigned int a;
    asm("{ .reg .u64 t; cvta.to.shared.u64 t, %1; cvt.u32.u64 %0, t; }"
        : "=r"(a) : "l"(p));
    return a;
}
__device__ __forceinline__ void cpa16(unsigned int dst, const void* src) {
    asm volatile("cp.async.cg.shared.global [%0], [%1], 16;"
                 :: "r"(dst), "l"(src) : "memory");
}
#define CP_COMMIT() asm volatile("cp.async.commit_group;" ::: "memory")
#define CP_WAIT1()  asm volatile("cp.async.wait_group 1;" ::: "memory")
#define CP_WAIT0()  asm volatile("cp.async.wait_group 0;" ::: "memory")

// ---------------- input projection: x = relu(ge * w + b) ----------------
__global__ void k_input(const float* __restrict__ ge,
                        const float* __restrict__ w,
                        const float* __restrict__ b) {
    int idx = blockIdx.x * 256 + threadIdx.x;   // over B*N*HID
    int c = idx & (HID - 1);
    float v = fmaf(ge[idx >> 8], w[c], b[c]);
    g_x0[idx] = v > 0.f ? v : 0.f;
}

// ---------------- fused pool: scores -> exp -> weighted partial + Z partial ----
// w1 streamed through a 2-stage cp.async smem pipeline (16 c-rows/stage).
__global__ void __launch_bounds__(256) k_pool_sb(const float* __restrict__ x,
                                                 const float* __restrict__ w1,
                                                 const float* __restrict__ b1,
                                                 const float* __restrict__ w2) {
    __shared__ float xs[16][HID];                       // 16 KB
    __shared__ __align__(16) float w1s[2][16][PL];      // 16 KB
    __shared__ float red[16][4];
    __shared__ float se[16];
    int b = blockIdx.x >> 7, seg = blockIdx.x & 127;
    int tid = threadIdx.x;
    long n0 = (long)b * NNODE + seg * 16;

    // load 16 x rows (1024 float4)
    const float4* s4 = (const float4*)(x + n0 * HID);
    float4* d4 = (float4*)xs;
#pragma unroll
    for (int k = 0; k < 4; k++) d4[tid + k * 256] = s4[tid + k * 256];

    // prologue: stage 0 of w1 (16 rows x 128 = 512 float4; 2 per thread)
    unsigned int w1s0 = smem_u32(w1s) + (unsigned int)tid * 16u;
    const float4* wsrc = (const float4*)w1 + tid;
#pragma unroll
    for (int k = 0; k < 2; k++) cpa16(w1s0 + k * 4096u, wsrc + k * 256);
    CP_COMMIT();

    int half = tid >> 7, p = tid & 127;
    float acc[8];
#pragma unroll
    for (int r = 0; r < 8; r++) acc[r] = 0.f;

    const int NS = HID / 16;   // 16 stages
    for (int s = 0; s < NS; s++) {
        int cur = s & 1;
        __syncthreads();               // prev compute done with buf cur^1 (s=0: xs fill)
        if (s + 1 < NS) {
            unsigned int dst = w1s0 + (unsigned int)(cur ^ 1) * 8192u;
            const float4* src = wsrc + (s + 1) * 512;
#pragma unroll
            for (int k = 0; k < 2; k++) cpa16(dst + k * 4096u, src + k * 256);
            CP_COMMIT();
        }
        if (s + 1 < NS) CP_WAIT1(); else CP_WAIT0();
        __syncthreads();               // buf cur visible
#pragma unroll
        for (int u4 = 0; u4 < 4; u4++) {
            int u = u4 * 4;
            float wv0 = w1s[cur][u + 0][p];
            float wv1 = w1s[cur][u + 1][p];
            float wv2 = w1s[cur][u + 2][p];
            float wv3 = w1s[cur][u + 3][p];
            int c = s * 16 + u;
#pragma unroll
            for (int r = 0; r < 8; r++) {
                float4 xv = *(const float4*)&xs[half * 8 + r][c];
                acc[r] = fmaf(xv.x, wv0, acc[r]);
                acc[r] = fmaf(xv.y, wv1, acc[r]);
                acc[r] = fmaf(xv.z, wv2, acc[r]);
                acc[r] = fmaf(xv.w, wv3, acc[r]);
            }
        }
    }
    float bv = b1[p], w2v = w2[p];
    int lane = tid & 31, wp = tid >> 5;
#pragma unroll
    for (int r = 0; r < 8; r++) {
        float v = tanhf(acc[r] + bv) * w2v;
#pragma unroll
        for (int off = 16; off; off >>= 1) v += __shfl_down_sync(0xffffffffu, v, off);
        if (lane == 0) red[half * 8 + r][wp & 3] = v;
    }
    __syncthreads();
    if (tid < 16) {
        float s = red[tid][0] + red[tid][1] + red[tid][2] + red[tid][3];
        float e = expf(s);
        se[tid] = e;
        float z = e;
#pragma unroll
        for (int off = 8; off; off >>= 1) z += __shfl_down_sync(0x0000ffffu, z, off, 16);
        if (tid == 0) g_zpart[b * 128 + seg] = z;
    }
    __syncthreads();
    float a = 0.f;
#pragma unroll
    for (int r = 0; r < 16; r++) a = fmaf(se[r], xs[r][tid], a);
    g_partial[(b * 128 + seg) * HID + tid] = a;
}

// ---------------- pool finalize: parallel reduce 128 partials + Z, divide ------
__global__ void k_pool_c2(float* __restrict__ outp) {
    __shared__ float chunks[4][64];
    __shared__ float zred[2];
    int b = blockIdx.x >> 2, cg = blockIdx.x & 3;
    int tid = threadIdx.x;
    int c = cg * 64 + (tid & 63), sc = tid >> 6;
    float a = 0.f;
#pragma unroll 8
    for (int k = 0; k < 32; k++)
        a += g_partial[(b * 128 + sc * 32 + k) * HID + c];
    chunks[sc][tid & 63] = a;
    if (tid < 32) {
        float z = g_zpart[b * 128 + tid] + g_zpart[b * 128 + 32 + tid]
                + g_zpart[b * 128 + 64 + tid] + g_zpart[b * 128 + 96 + tid];
#pragma unroll
        for (int off = 16; off; off >>= 1) z += __shfl_down_sync(0xffffffffu, z, off);
        if (tid == 0) zred[0] = z;
    }
    __syncthreads();
    if (tid < 64) {
        float t = chunks[0][tid] + chunks[1][tid] + chunks[2][tid] + chunks[3][tid];
        outp[b * HID + cg * 64 + tid] = t / zred[0];
    }
}

// ---------------- h = cur @ W, fused src/dst; W via cp.async pipeline ----------
// W streamed through a 2-stage 16-row smem pipeline: removes the W-LDG latency
// that held k_gemm 3.5x above its issue floor (occ is grid-limited, so the
// latency must be removed, not hidden by more warps).
__global__ void __launch_bounds__(256) k_gemm(const float* __restrict__ xin,
                                              const float* __restrict__ W,
                                              const float* __restrict__ asrc,
                                              const float* __restrict__ adst) {
    __shared__ float xs[8][HID];                        // 8 KB
    __shared__ __align__(16) float ws[2][16][HID];      // 32 KB
    __shared__ float sred[8][8], dred[8][8];
    int row0 = blockIdx.x * 8;
    int tid = threadIdx.x;

    // xs fill (512 float4)
    const float4* s4 = (const float4*)(xin + row0 * HID);
    float4* d4 = (float4*)xs;
#pragma unroll
    for (int k = 0; k < 2; k++) d4[tid + k * 256] = s4[tid + k * 256];

    // prologue: stage 0 of W (16 rows x 256 = 1024 float4; 4 per thread)
    unsigned int ws0 = smem_u32(ws) + (unsigned int)tid * 16u;
    const float4* wsrc = (const float4*)W + tid;
#pragma unroll
    for (int k = 0; k < 4; k++) cpa16(ws0 + k * 4096u, wsrc + k * 256);
    CP_COMMIT();

    float acc[8];
#pragma unroll
    for (int r = 0; r < 8; r++) acc[r] = 0.f;

    const int NS = HID / 16;   // 16 stages
    for (int s = 0; s < NS; s++) {
        int cur = s & 1;
        __syncthreads();               // prev compute done with buf cur^1 (s=0: xs fill)
        if (s + 1 < NS) {
            unsigned int dst = ws0 + (unsigned int)(cur ^ 1) * 16384u;
            const float4* src = wsrc + (s + 1) * 1024;
#pragma unroll
            for (int k = 0; k < 4; k++) cpa16(dst + k * 4096u, src + k * 256);
            CP_COMMIT();
        }
        if (s + 1 < NS) CP_WAIT1(); else CP_WAIT0();
        __syncthreads();               // buf cur visible
#pragma unroll
        for (int u4 = 0; u4 < 4; u4++) {
            int u = u4 * 4;
            float wv0 = ws[cur][u + 0][tid];
            float wv1 = ws[cur][u + 1][tid];
            float wv2 = ws[cur][u + 2][tid];
            float wv3 = ws[cur][u + 3][tid];
            int c = s * 16 + u;
#pragma unroll
            for (int r = 0; r < 8; r++) {
                float4 xv = *(const float4*)&xs[r][c];
                acc[r] = fmaf(xv.x, wv0, acc[r]);
                acc[r] = fmaf(xv.y, wv1, acc[r]);
                acc[r] = fmaf(xv.z, wv2, acc[r]);
                acc[r] = fmaf(xv.w, wv3, acc[r]);
            }
        }
    }
#pragma unroll
    for (int r = 0; r < 8; r++) g_h[(row0 + r) * HID + tid] = acc[r];

    float as = asrc[tid], ad = adst[tid];
    int lane = tid & 31, wp = tid >> 5;
#pragma unroll
    for (int r = 0; r < 8; r++) {
        float vs = acc[r] * as, vd = acc[r] * ad;
#pragma unroll
        for (int off = 16; off; off >>= 1) {
            vs += __shfl_down_sync(0xffffffffu, vs, off);
            vd += __shfl_down_sync(0xffffffffu, vd, off);
        }
        if (lane == 0) { sred[r][wp] = vs; dred[r][wp] = vd; }
    }
    __syncthreads();
    if (tid < 32) {
        int r = tid & 7, hh = tid >> 3;
        float s = sred[r][2 * hh] + sred[r][2 * hh + 1];
        float d = dred[r][2 * hh] + dred[r][2 * hh + 1];
        int o = (row0 + r) * NH + hh;
        g_spk[o] = make_float4(s, expf(s), expf(0.2f * s), 0.f);
        g_dpk[o] = make_float4(d, expf(d), expf(0.2f * d), 0.f);
    }
}

// ---------------- GAT aggregation + ELU ----------------
// j-pair half-warp phase-2 (R13 win) + register prefetch of next tile's
// adj int4 (DRAM ~400-580cyc!) and dq float4s, issued a full tile early.
#define TI 16
#define TJ 16
#define ESLAB 272   // TJ*TI + 16 pad floats per head slab
__global__ void __launch_bounds__(256) k_agg(const int* __restrict__ adj,
                                             float* __restrict__ outn) {
    __shared__ __align__(16) float hs[2][TJ][HID];      // 32 KB (double buffer)
    __shared__ __align__(16) float es2[NH * ESLAB];     // 4.25 KB, [h][j][i]
    __shared__ float zs[TI * NH];                       // 64

    int b  = blockIdx.x >> 7;              // 128 i-tiles per batch
    int i0 = (blockIdx.x & 127) * TI;
    int tid = threadIdx.x;

    if (tid < TI * NH) zs[tid] = 0.f;

    int i_p1 = tid & 15;
    int h_p1 = (tid >> 4) & 3;
    int jg   = tid >> 6;                   // j = jg*4 + rep, rep 0..3

    float4 sq = g_spk[(b * NNODE + i0 + i_p1) * NH + h_p1];
    const int* __restrict__ arow = adj + b * NNODE * NNODE + (i0 + i_p1) * NNODE + jg * 4;
    const float4* __restrict__ dtab = g_dpk + (b * NNODE) * NH + jg * 4 * NH + h_p1;
    float* __restrict__ eout = es2 + h_p1 * ESLAB + jg * 4 * 16 + i_p1;
    float zloc = 0.f;

    // phase-2 mapping: warp w covers cols [32w,32w+32); hh uniform per warp-pair
    int w    = tid >> 5;
    int lane = tid & 31;
    int cl   = lane & 15;
    int jpar = lane >> 4;                  // 0: even j, 1: odd j
    int hh   = tid >> 6;
    const float* eslab = es2 + hh * ESLAB;
    int c1 = 32 * w + cl + 16 * jpar;
    int c2 = 32 * w + cl + 16 * (1 - jpar);

    unsigned int hs0 = smem_u32(hs) + (unsigned int)tid * 16u;
    const float4* hsrc_base = (const float4*)(g_h + b * NNODE * HID) + tid;

    unsigned long long accP[8], accQ[8];
#pragma unroll
    for (int r = 0; r < 8; r++) { accP[r] = 0ull; accQ[r] = 0ull; }

    // prologue: h tile 0 + table prefetch for tile 0
    {
        const float4* src = hsrc_base;
#pragma unroll
        for (int k = 0; k < 4; k++) cpa16(hs0 + k * 4096u, src + k * 256);
        CP_COMMIT();
    }
    int4 aaN = *(const int4*)(arow);
    float4 dqN0 = dtab[0];
    float4 dqN1 = dtab[NH];
    float4 dqN2 = dtab[2 * NH];
    float4 dqN3 = dtab[3 * NH];

    const int NT = NNODE / TJ;   // 128 tiles
    for (int jt = 0; jt < NT; jt++) {
        int j0 = jt * TJ;
        int cur = jt & 1;
        __syncthreads();   // phase2(jt-1) done: es2 free, buf cur^1 free
        if (jt + 1 < NT) {
            const float4* src = hsrc_base + (j0 + TJ) * (HID / 4);
            unsigned int dst = hs0 + (unsigned int)(cur ^ 1) * 16384u;
#pragma unroll
            for (int k = 0; k < 4; k++) cpa16(dst + k * 4096u, src + k * 256);
            CP_COMMIT();
        }
        // phase 1: uses prefetched aaN/dqN
        {
            int av[4] = {aaN.x, aaN.y, aaN.z, aaN.w};
            float4 dqv[4] = {dqN0, dqN1, dqN2, dqN3};
#pragma unroll
            for (int rep = 0; rep < 4; rep++) {
                float4 dq = dqv[rep];
                float sv = sq.x + dq.x;
                float e = 0.f;
                if (av[rep] > 0) e = (sv >= 0.f) ? sq.y * dq.y : sq.z * dq.z;
                eout[rep * 16] = e;
                zloc += e;
            }
        }
        // prefetch tables for tile jt+1 (a full tile of slack to land)
        if (jt + 1 < NT) {
            aaN = *(const int4*)(arow + j0 + TJ);
            const float4* dqn = dtab + (j0 + TJ) * NH;
            dqN0 = dqn[0];
            dqN1 = dqn[NH];
            dqN2 = dqn[2 * NH];
            dqN3 = dqn[3 * NH];
        }
        if (jt + 1 < NT) CP_WAIT1(); else CP_WAIT0();
        __syncthreads();   // hs[cur] filled + es2 visible
        // phase 2: j-pairs; lane handles j = 2t + jpar for cols c1, c2
#pragma unroll 4
        for (int t = 0; t < TJ / 2; t++) {
            int jj = 2 * t + jpar;
            const ulonglong2* ep = (const ulonglong2*)(eslab + jj * 16);
            ulonglong2 e0 = ep[0];
            ulonglong2 e1 = ep[1];
            const float* hrow = hs[cur][jj];
            unsigned long long hv1 = pack2(hrow[c1]);
            unsigned long long hv2 = pack2(hrow[c2]);
            ulonglong2 e2 = ep[2];
            ulonglong2 e3 = ep[3];
            accP[0] = fma2(e0.x, hv1, accP[0]);  accQ[0] = fma2(e0.x, hv2, accQ[0]);
            accP[1] = fma2(e0.y, hv1, accP[1]);  accQ[1] = fma2(e0.y, hv2, accQ[1]);
            accP[2] = fma2(e1.x, hv1, accP[2]);  accQ[2] = fma2(e1.x, hv2, accQ[2]);
            accP[3] = fma2(e1.y, hv1, accP[3]);  accQ[3] = fma2(e1.y, hv2, accQ[3]);
            accP[4] = fma2(e2.x, hv1, accP[4]);  accQ[4] = fma2(e2.x, hv2, accQ[4]);
            accP[5] = fma2(e2.y, hv1, accP[5]);  accQ[5] = fma2(e2.y, hv2, accQ[5]);
            accP[6] = fma2(e3.x, hv1, accP[6]);  accQ[6] = fma2(e3.x, hv2, accQ[6]);
            accP[7] = fma2(e3.y, hv1, accP[7]);  accQ[7] = fma2(e3.y, hv2, accQ[7]);
        }
    }
    atomicAdd(&zs[i_p1 * NH + h_p1], zloc);

    // cross-half combine: fA = colA(even)+colA(odd), fB = colB(even)+colB(odd)
    unsigned long long fA[8], fB[8];
#pragma unroll
    for (int r = 0; r < 8; r++) {
        unsigned long long oq = __shfl_down_sync(0xffffffffu, accQ[r], 16);
        unsigned long long op = __shfl_down_sync(0xffffffffu, accP[r], 16);
        fA[r] = add2(accP[r], oq);
        fB[r] = add2(accQ[r], op);
    }
    __syncthreads();   // zs complete
    if (lane < 16) {
        int colA = 32 * w + cl, colB = colA + 16;
#pragma unroll
        for (int r = 0; r < 8; r++) {
            int ia = 2 * r, ib = 2 * r + 1;
            float zA = zs[ia * NH + hh], zB = zs[ib * NH + hh];
            float a0, a1, b0, b1;
            unpack2(fA[r], a0, a1);
            unpack2(fB[r], b0, b1);
            float ra0 = a0 / zA, ra1 = a1 / zB;
            float rb0 = b0 / zA, rb1 = b1 / zB;
            long base = (long)(b * NNODE + i0) * HID;
            outn[base + (long)ia * HID + colA] = (ra0 > 0.f) ? ra0 : expm1f(ra0);
            outn[base + (long)ib * HID + colA] = (ra1 > 0.f) ? ra1 : expm1f(ra1);
            outn[base + (long)ia * HID + colB] = (rb0 > 0.f) ? rb0 : expm1f(rb0);
            outn[base + (long)ib * HID + colB] = (rb1 > 0.f) ? rb1 : expm1f(rb1);
        }
    }
}

// ---------------- host orchestration ----------------
static void run_pool(const float* x, const float* w1, const float* b1,
                     const float* w2, float* outp) {
    k_pool_sb<<<BB * 128, 256>>>(x, w1, b1, w2);
    k_pool_c2<<<BB * 4, 256>>>(outp);
}

extern "C" void kernel_launch(void* const* d_in, const int* in_sizes, int n_in,
                              void* d_out, int out_size) {
    const float* ge       = (const float*)d_in[0];
    const int*   adj      = (const int*)  d_in[1];
    const float* in_w     = (const float*)d_in[2];
    const float* in_b     = (const float*)d_in[3];
    const float* proj_w   = (const float*)d_in[4];   // [2,256,256]
    const float* attn_src = (const float*)d_in[5];   // [2,4,64]
    const float* attn_dst = (const float*)d_in[6];
    const float* pool_w1  = (const float*)d_in[7];   // [2,256,128]
    const float* pool_b1  = (const float*)d_in[8];   // [2,128]
    const float* pool_w2  = (const float*)d_in[9];   // [2,128]
    const float* ip_w1    = (const float*)d_in[11];  // [256,128]
    const float* ip_b1    = (const float*)d_in[12];
    const float* ip_w2    = (const float*)d_in[13];

    float* out = (float*)d_out;
    const int NODE_SZ = BB * NNODE * HID;            // 1048576
    float* raw_pooled = out;
    float* node0 = out + BB * HID;
    float* node1 = node0 + NODE_SZ;
    float* pooled0 = node1 + NODE_SZ;
    float* pooled1 = pooled0 + BB * HID;

    float* x0 = nullptr;
    cudaGetSymbolAddress((void**)&x0, g_x0);

    // input projection
    k_input<<<BB * NNODE * HID / 256, 256>>>(ge, in_w, in_b);

    // raw pooled (on x0)
    run_pool(x0, ip_w1, ip_b1, ip_w2, raw_pooled);

    // layer 0
    k_gemm<<<BB * NNODE / 8, 256>>>(x0, proj_w, attn_src, attn_dst);
    k_agg<<<BB * (NNODE / TI), 256>>>(adj, node0);
    run_pool(node0, pool_w1, pool_b1, pool_w2, pooled0);

    // layer 1
    k_gemm<<<BB * NNODE / 8, 256>>>(node0, proj_w + HID * HID,
                                    attn_src + NH * DD, attn_dst + NH * DD);
    k_agg<<<BB * (NNODE / TI), 256>>>(adj, node1);
    run_pool(node1, pool_w1 + HID * PL, pool_b1 + PL, pool_w2 + PL, pooled1);
}

// round 17
// speedup vs baseline: 1.0376x; 1.0376x over previous
#include <cuda_runtime.h>
#include <math.h>

#define BB   2
#define NNODE 2048
#define HID  256
#define NH   4
#define DD   64
#define PL   128

// ---------------- scratch (device globals; no allocation allowed) ----------------
__device__ float g_x0[BB*NNODE*HID];       // input-proj output (4 MB)
__device__ float g_h[BB*NNODE*HID];        // per-layer projected features (4 MB)
__device__ float4 g_spk[BB*NNODE*NH];      // (src, exp(src), exp(.2src), 0)
__device__ float4 g_dpk[BB*NNODE*NH];      // (dst, exp(dst), exp(.2dst), 0)
__device__ float g_partial[BB*128*HID];    // pool partial weighted sums (unnormalized)
__device__ float g_zpart[BB*128];          // pool partial Z

// ---------------- packed f32x2 helpers (sm_103a) ----------------
__device__ __forceinline__ unsigned long long pack2(float v) {
    unsigned long long r;
    asm("mov.b64 %0, {%1, %1};" : "=l"(r) : "f"(v));
    return r;
}
__device__ __forceinline__ void unpack2(unsigned long long v, float& lo, float& hi) {
    asm("mov.b64 {%0, %1}, %2;" : "=f"(lo), "=f"(hi) : "l"(v));
}
__device__ __forceinline__ unsigned long long fma2(unsigned long long a,
                                                   unsigned long long b,
                                                   unsigned long long c) {
    unsigned long long d;
    asm("fma.rn.f32x2 %0, %1, %2, %3;" : "=l"(d) : "l"(a), "l"(b), "l"(c));
    return d;
}
__device__ __forceinline__ unsigned long long add2(unsigned long long a,
                                                   unsigned long long b) {
    unsigned long long d;
    asm("add.rn.f32x2 %0, %1, %2;" : "=l"(d) : "l"(a), "l"(b));
    return d;
}
__device__ __forceinline__ unsigned int smem_u32(const void* p) {
    unsigned int a;
    asm("{ .reg .u64 t; cvta.to.shared.u64 t, %1; cvt.u32.u64 %0, t; }"
        : "=r"(a) : "l"(p));
    return a;
}
__device__ __forceinline__ void cpa16(unsigned int dst, const void* src) {
    asm volatile("cp.async.cg.shared.global [%0], [%1], 16;"
                 :: "r"(dst), "l"(src) : "memory");
}
#define CP_COMMIT() asm volatile("cp.async.commit_group;" ::: "memory")
#define CP_WAIT1()  asm volatile("cp.async.wait_group 1;" ::: "memory")
#define CP_WAIT0()  asm volatile("cp.async.wait_group 0;" ::: "memory")

// ---------------- input projection: x = relu(ge * w + b) ----------------
__global__ void k_input(const float* __restrict__ ge,
                        const float* __restrict__ w,
                        const float* __restrict__ b) {
    int idx = blockIdx.x * 256 + threadIdx.x;   // over B*N*HID
    int c = idx & (HID - 1);
    float v = fmaf(ge[idx >> 8], w[c], b[c]);
    g_x0[idx] = v > 0.f ? v : 0.f;
}

// ---------------- fused pool (R13 form — measured best): scores->exp->partials --
__global__ void __launch_bounds__(256) k_pool_sb(const float* __restrict__ x,
                                                 const float* __restrict__ w1,
                                                 const float* __restrict__ b1,
                                                 const float* __restrict__ w2) {
    __shared__ float xs[16][HID];      // 16 KB
    __shared__ float red[16][4];
    __shared__ float se[16];
    int b = blockIdx.x >> 7, seg = blockIdx.x & 127;
    int tid = threadIdx.x;
    long n0 = (long)b * NNODE + seg * 16;

    const float4* s4 = (const float4*)(x + n0 * HID);
    float4* d4 = (float4*)xs;
#pragma unroll
    for (int k = 0; k < 4; k++) d4[tid + k * 256] = s4[tid + k * 256];
    __syncthreads();

    int half = tid >> 7, p = tid & 127;
    float acc[8];
#pragma unroll
    for (int r = 0; r < 8; r++) acc[r] = 0.f;
    for (int c = 0; c < HID; c += 4) {
        float wv0 = w1[(c + 0) * PL + p];
        float wv1 = w1[(c + 1) * PL + p];
        float wv2 = w1[(c + 2) * PL + p];
        float wv3 = w1[(c + 3) * PL + p];
#pragma unroll
        for (int r = 0; r < 8; r++) {
            float4 xv = *(const float4*)&xs[half * 8 + r][c];
            acc[r] = fmaf(xv.x, wv0, acc[r]);
            acc[r] = fmaf(xv.y, wv1, acc[r]);
            acc[r] = fmaf(xv.z, wv2, acc[r]);
            acc[r] = fmaf(xv.w, wv3, acc[r]);
        }
    }
    float bv = b1[p], w2v = w2[p];
    int lane = tid & 31, wp = tid >> 5;
#pragma unroll
    for (int r = 0; r < 8; r++) {
        float v = tanhf(acc[r] + bv) * w2v;
#pragma unroll
        for (int off = 16; off; off >>= 1) v += __shfl_down_sync(0xffffffffu, v, off);
        if (lane == 0) red[half * 8 + r][wp & 3] = v;
    }
    __syncthreads();
    if (tid < 16) {
        float s = red[tid][0] + red[tid][1] + red[tid][2] + red[tid][3];
        float e = expf(s);
        se[tid] = e;
        float z = e;
#pragma unroll
        for (int off = 8; off; off >>= 1) z += __shfl_down_sync(0x0000ffffu, z, off, 16);
        if (tid == 0) g_zpart[b * 128 + seg] = z;
    }
    __syncthreads();
    float a = 0.f;
#pragma unroll
    for (int r = 0; r < 16; r++) a = fmaf(se[r], xs[r][tid], a);
    g_partial[(b * 128 + seg) * HID + tid] = a;
}

// ---------------- pool finalize: parallel reduce 128 partials + Z, divide ------
__global__ void k_pool_c2(float* __restrict__ outp) {
    __shared__ float chunks[4][64];
    __shared__ float zred[2];
    int b = blockIdx.x >> 2, cg = blockIdx.x & 3;
    int tid = threadIdx.x;
    int c = cg * 64 + (tid & 63), sc = tid >> 6;
    float a = 0.f;
#pragma unroll 8
    for (int k = 0; k < 32; k++)
        a += g_partial[(b * 128 + sc * 32 + k) * HID + c];
    chunks[sc][tid & 63] = a;
    if (tid < 32) {
        float z = g_zpart[b * 128 + tid] + g_zpart[b * 128 + 32 + tid]
                + g_zpart[b * 128 + 64 + tid] + g_zpart[b * 128 + 96 + tid];
#pragma unroll
        for (int off = 16; off; off >>= 1) z += __shfl_down_sync(0xffffffffu, z, off);
        if (tid == 0) zred[0] = z;
    }
    __syncthreads();
    if (tid < 64) {
        float t = chunks[0][tid] + chunks[1][tid] + chunks[2][tid] + chunks[3][tid];
        outp[b * HID + cg * 64 + tid] = t / zred[0];
    }
}

// ---------------- h = cur @ W (R14 form — measured best): cp.async W pipeline ---
__global__ void __launch_bounds__(256) k_gemm(const float* __restrict__ xin,
                                              const float* __restrict__ W,
                                              const float* __restrict__ asrc,
                                              const float* __restrict__ adst) {
    __shared__ float xs[8][HID];                        // 8 KB
    __shared__ __align__(16) float ws[2][16][HID];      // 32 KB
    __shared__ float sred[8][8], dred[8][8];
    int row0 = blockIdx.x * 8;
    int tid = threadIdx.x;

    // xs fill (512 float4)
    const float4* s4 = (const float4*)(xin + row0 * HID);
    float4* d4 = (float4*)xs;
#pragma unroll
    for (int k = 0; k < 2; k++) d4[tid + k * 256] = s4[tid + k * 256];

    // prologue: stage 0 of W (16 rows x 256 = 1024 float4; 4 per thread)
    unsigned int ws0 = smem_u32(ws) + (unsigned int)tid * 16u;
    const float4* wsrc = (const float4*)W + tid;
#pragma unroll
    for (int k = 0; k < 4; k++) cpa16(ws0 + k * 4096u, wsrc + k * 256);
    CP_COMMIT();

    float acc[8];
#pragma unroll
    for (int r = 0; r < 8; r++) acc[r] = 0.f;

    const int NS = HID / 16;   // 16 stages
    for (int s = 0; s < NS; s++) {
        int cur = s & 1;
        __syncthreads();               // prev compute done with buf cur^1 (s=0: xs fill)
        if (s + 1 < NS) {
            unsigned int dst = ws0 + (unsigned int)(cur ^ 1) * 16384u;
            const float4* src = wsrc + (s + 1) * 1024;
#pragma unroll
            for (int k = 0; k < 4; k++) cpa16(dst + k * 4096u, src + k * 256);
            CP_COMMIT();
        }
        if (s + 1 < NS) CP_WAIT1(); else CP_WAIT0();
        __syncthreads();               // buf cur visible
#pragma unroll
        for (int u4 = 0; u4 < 4; u4++) {
            int u = u4 * 4;
            float wv0 = ws[cur][u + 0][tid];
            float wv1 = ws[cur][u + 1][tid];
            float wv2 = ws[cur][u + 2][tid];
            float wv3 = ws[cur][u + 3][tid];
            int c = s * 16 + u;
#pragma unroll
            for (int r = 0; r < 8; r++) {
                float4 xv = *(const float4*)&xs[r][c];
                acc[r] = fmaf(xv.x, wv0, acc[r]);
                acc[r] = fmaf(xv.y, wv1, acc[r]);
                acc[r] = fmaf(xv.z, wv2, acc[r]);
                acc[r] = fmaf(xv.w, wv3, acc[r]);
            }
        }
    }
#pragma unroll
    for (int r = 0; r < 8; r++) g_h[(row0 + r) * HID + tid] = acc[r];

    float as = asrc[tid], ad = adst[tid];
    int lane = tid & 31, wp = tid >> 5;
#pragma unroll
    for (int r = 0; r < 8; r++) {
        float vs = acc[r] * as, vd = acc[r] * ad;
#pragma unroll
        for (int off = 16; off; off >>= 1) {
            vs += __shfl_down_sync(0xffffffffu, vs, off);
            vd += __shfl_down_sync(0xffffffffu, vd, off);
        }
        if (lane == 0) { sred[r][wp] = vs; dred[r][wp] = vd; }
    }
    __syncthreads();
    if (tid < 32) {
        int r = tid & 7, hh = tid >> 3;
        float s = sred[r][2 * hh] + sred[r][2 * hh + 1];
        float d = dred[r][2 * hh] + dred[r][2 * hh + 1];
        int o = (row0 + r) * NH + hh;
        g_spk[o] = make_float4(s, expf(s), expf(0.2f * s), 0.f);
        g_dpk[o] = make_float4(d, expf(d), expf(0.2f * d), 0.f);
    }
}

// ---------------- GAT aggregation + ELU (R13 form — measured best) -------------
// j-pair half-warp phase-2; double-buffered cp.async h-tiles; no table prefetch.
#define TI 16
#define TJ 16
#define ESLAB 272   // TJ*TI + 16 pad floats per head slab
__global__ void __launch_bounds__(256) k_agg(const int* __restrict__ adj,
                                             float* __restrict__ outn) {
    __shared__ __align__(16) float hs[2][TJ][HID];      // 32 KB (double buffer)
    __shared__ __align__(16) float es2[NH * ESLAB];     // 4.25 KB, [h][j][i]
    __shared__ float zs[TI * NH];                       // 64

    int b  = blockIdx.x >> 7;              // 128 i-tiles per batch
    int i0 = (blockIdx.x & 127) * TI;
    int tid = threadIdx.x;

    if (tid < TI * NH) zs[tid] = 0.f;

    int i_p1 = tid & 15;
    int h_p1 = (tid >> 4) & 3;
    int jg   = tid >> 6;                   // j = jg*4 + rep, rep 0..3

    float4 sq = g_spk[(b * NNODE + i0 + i_p1) * NH + h_p1];
    const int* __restrict__ arow = adj + b * NNODE * NNODE + (i0 + i_p1) * NNODE + jg * 4;
    const float4* __restrict__ dtab = g_dpk + (b * NNODE) * NH + jg * 4 * NH + h_p1;
    float* __restrict__ eout = es2 + h_p1 * ESLAB + jg * 4 * 16 + i_p1;
    float zloc = 0.f;

    int w    = tid >> 5;
    int lane = tid & 31;
    int cl   = lane & 15;
    int jpar = lane >> 4;                  // 0: even j, 1: odd j
    int hh   = tid >> 6;
    const float* eslab = es2 + hh * ESLAB;
    int c1 = 32 * w + cl + 16 * jpar;
    int c2 = 32 * w + cl + 16 * (1 - jpar);

    unsigned int hs0 = smem_u32(hs) + (unsigned int)tid * 16u;
    const float4* hsrc_base = (const float4*)(g_h + b * NNODE * HID) + tid;

    unsigned long long accP[8], accQ[8];
#pragma unroll
    for (int r = 0; r < 8; r++) { accP[r] = 0ull; accQ[r] = 0ull; }

    // prologue: issue tile 0 into buffer 0
    {
        const float4* src = hsrc_base;
#pragma unroll
        for (int k = 0; k < 4; k++) cpa16(hs0 + k * 4096u, src + k * 256);
        CP_COMMIT();
    }

    const int NT = NNODE / TJ;   // 128 tiles
    for (int jt = 0; jt < NT; jt++) {
        int j0 = jt * TJ;
        int cur = jt & 1;
        __syncthreads();   // phase2(jt-1) done: es2 free, buf cur^1 free
        if (jt + 1 < NT) {
            const float4* src = hsrc_base + (j0 + TJ) * (HID / 4);
            unsigned int dst = hs0 + (unsigned int)(cur ^ 1) * 16384u;
#pragma unroll
            for (int k = 0; k < 4; k++) cpa16(dst + k * 4096u, src + k * 256);
            CP_COMMIT();
        }
        // phase 1: e for (i_p1, j = jg*4+rep, h_p1); adj + dq batched
        {
            int4 aa = *(const int4*)(arow + j0);
            const float4* dq4 = dtab + j0 * NH;
            float4 dq0 = dq4[0 * NH];
            float4 dq1 = dq4[1 * NH];
            float4 dq2 = dq4[2 * NH];
            float4 dq3 = dq4[3 * NH];
            int av[4] = {aa.x, aa.y, aa.z, aa.w};
            float4 dqv[4] = {dq0, dq1, dq2, dq3};
#pragma unroll
            for (int rep = 0; rep < 4; rep++) {
                float4 dq = dqv[rep];
                float sv = sq.x + dq.x;
                float e = 0.f;
                if (av[rep] > 0) e = (sv >= 0.f) ? sq.y * dq.y : sq.z * dq.z;
                eout[rep * 16] = e;
                zloc += e;
            }
        }
        if (jt + 1 < NT) CP_WAIT1(); else CP_WAIT0();
        __syncthreads();   // hs[cur] filled + es2 visible
        // phase 2: j-pairs; lane handles j = 2t + jpar for cols c1, c2
#pragma unroll 4
        for (int t = 0; t < TJ / 2; t++) {
            int jj = 2 * t + jpar;
            const ulonglong2* ep = (const ulonglong2*)(eslab + jj * 16);
            ulonglong2 e0 = ep[0];
            ulonglong2 e1 = ep[1];
            const float* hrow = hs[cur][jj];
            unsigned long long hv1 = pack2(hrow[c1]);
            unsigned long long hv2 = pack2(hrow[c2]);
            ulonglong2 e2 = ep[2];
            ulonglong2 e3 = ep[3];
            accP[0] = fma2(e0.x, hv1, accP[0]);  accQ[0] = fma2(e0.x, hv2, accQ[0]);
            accP[1] = fma2(e0.y, hv1, accP[1]);  accQ[1] = fma2(e0.y, hv2, accQ[1]);
            accP[2] = fma2(e1.x, hv1, accP[2]);  accQ[2] = fma2(e1.x, hv2, accQ[2]);
            accP[3] = fma2(e1.y, hv1, accP[3]);  accQ[3] = fma2(e1.y, hv2, accQ[3]);
            accP[4] = fma2(e2.x, hv1, accP[4]);  accQ[4] = fma2(e2.x, hv2, accQ[4]);
            accP[5] = fma2(e2.y, hv1, accP[5]);  accQ[5] = fma2(e2.y, hv2, accQ[5]);
            accP[6] = fma2(e3.x, hv1, accP[6]);  accQ[6] = fma2(e3.x, hv2, accQ[6]);
            accP[7] = fma2(e3.y, hv1, accP[7]);  accQ[7] = fma2(e3.y, hv2, accQ[7]);
        }
    }
    atomicAdd(&zs[i_p1 * NH + h_p1], zloc);

    // cross-half combine: fA = colA(even)+colA(odd), fB = colB(even)+colB(odd)
    unsigned long long fA[8], fB[8];
#pragma unroll
    for (int r = 0; r < 8; r++) {
        unsigned long long oq = __shfl_down_sync(0xffffffffu, accQ[r], 16);
        unsigned long long op = __shfl_down_sync(0xffffffffu, accP[r], 16);
        fA[r] = add2(accP[r], oq);
        fB[r] = add2(accQ[r], op);
    }
    __syncthreads();   // zs complete
    if (lane < 16) {
        int colA = 32 * w + cl, colB = colA + 16;
#pragma unroll
        for (int r = 0; r < 8; r++) {
            int ia = 2 * r, ib = 2 * r + 1;
            float zA = zs[ia * NH + hh], zB = zs[ib * NH + hh];
            float a0, a1, b0, b1;
            unpack2(fA[r], a0, a1);
            unpack2(fB[r], b0, b1);
            float ra0 = a0 / zA, ra1 = a1 / zB;
            float rb0 = b0 / zA, rb1 = b1 / zB;
            long base = (long)(b * NNODE + i0) * HID;
            outn[base + (long)ia * HID + colA] = (ra0 > 0.f) ? ra0 : expm1f(ra0);
            outn[base + (long)ib * HID + colA] = (ra1 > 0.f) ? ra1 : expm1f(ra1);
            outn[base + (long)ia * HID + colB] = (rb0 > 0.f) ? rb0 : expm1f(rb0);
            outn[base + (long)ib * HID + colB] = (rb1 > 0.f) ? rb1 : expm1f(rb1);
        }
    }
}

// ---------------- host orchestration ----------------
static void run_pool(const float* x, const float* w1, const float* b1,
                     const float* w2, float* outp) {
    k_pool_sb<<<BB * 128, 256>>>(x, w1, b1, w2);
    k_pool_c2<<<BB * 4, 256>>>(outp);
}

extern "C" void kernel_launch(void* const* d_in, const int* in_sizes, int n_in,
                              void* d_out, int out_size) {
    const float* ge       = (const float*)d_in[0];
    const int*   adj      = (const int*)  d_in[1];
    const float* in_w     = (const float*)d_in[2];
    const float* in_b     = (const float*)d_in[3];
    const float* proj_w   = (const float*)d_in[4];   // [2,256,256]
    const float* attn_src = (const float*)d_in[5];   // [2,4,64]
    const float* attn_dst = (const float*)d_in[6];
    const float* pool_w1  = (const float*)d_in[7];   // [2,256,128]
    const float* pool_b1  = (const float*)d_in[8];   // [2,128]
    const float* pool_w2  = (const float*)d_in[9];   // [2,128]
    const float* ip_w1    = (const float*)d_in[11];  // [256,128]
    const float* ip_b1    = (const float*)d_in[12];
    const float* ip_w2    = (const float*)d_in[13];

    float* out = (float*)d_out;
    const int NODE_SZ = BB * NNODE * HID;            // 1048576
    float* raw_pooled = out;
    float* node0 = out + BB * HID;
    float* node1 = node0 + NODE_SZ;
    float* pooled0 = node1 + NODE_SZ;
    float* pooled1 = pooled0 + BB * HID;

    float* x0 = nullptr;
    cudaGetSymbolAddress((void**)&x0, g_x0);

    // input projection
    k_input<<<BB * NNODE * HID / 256, 256>>>(ge, in_w, in_b);

    // raw pooled (on x0)
    run_pool(x0, ip_w1, ip_b1, ip_w2, raw_pooled);

    // layer 0
    k_gemm<<<BB * NNODE / 8, 256>>>(x0, proj_w, attn_src, attn_dst);
    k_agg<<<BB * (NNODE / TI), 256>>>(adj, node0);
    run_pool(node0, pool_w1, pool_b1, pool_w2, pooled0);

    // layer 1
    k_gemm<<<BB * NNODE / 8, 256>>>(node0, proj_w + HID * HID,
                                    attn_src + NH * DD, attn_dst + NH * DD);
    k_agg<<<BB * (NNODE / TI), 256>>>(adj, node1);
    run_pool(node1, pool_w1 + HID * PL, pool_b1 + PL, pool_w2 + PL, pooled1);
}